// round 1
// baseline (speedup 1.0000x reference)
#include <cuda_runtime.h>
#include <math.h>
#include <stdint.h>

// Problem constants (derived at runtime too, buffers sized for these)
#define NMAX 50176      // >= 50000, multiple of 64
#define EMAX 800000

// ---------------- scratch (device globals; no allocations allowed) ----------
__device__ float g_h  [NMAX * 128];   // post-GEMM1 / post-LN-ELU features
__device__ float g_xl [NMAX * 256];   // per-layer lin_l output [N, HEADS*H2]
__device__ float g_xr [NMAX * 256];   // per-layer lin_r output
__device__ float g_alpha[EMAX * 4];   // per-edge per-head attention logits
__device__ float g_m  [NMAX * 4];     // segment max
__device__ float g_den[NMAX * 4];     // segment sum of exp
__device__ float g_agg[NMAX * 64];    // aggregated (head-mean already folded)
__device__ float g_h1 [NMAX * 64];    // layer1 output (residual source)
__device__ float g_h2 [NMAX * 64];    // layer2 output

// ---------------- helpers ----------------------------------------------------
__device__ __forceinline__ float eluf(float x) { return x > 0.f ? x : expm1f(x); }

__device__ __forceinline__ void atomicMaxF(float* addr, float v) {
    // signed-max for non-negative floats, unsigned-min for negative floats.
    if (v >= 0.f) atomicMax((int*)addr, __float_as_int(v));
    else          atomicMin((unsigned int*)addr, __float_as_uint(v));
}

// ---------------- generic SGEMM: C[M,Nc] = A[M,K] @ W[K,Nc] + bias -----------
// BM=BN=64, BK=16, 256 threads, 4x4 micro-tile per thread. K % 16 == 0.
__global__ void sgemm_bias(const float* __restrict__ A, const float* __restrict__ W,
                           const float* __restrict__ bias, float* __restrict__ C,
                           int M, int K, int Nc)
{
    __shared__ float As[16][64];
    __shared__ float Bs[16][64];

    const int tid = threadIdx.x;
    const int tx = tid & 15;        // col group 0..15
    const int ty = tid >> 4;        // row group 0..15
    const int rowBase = blockIdx.y * 64;
    const int colBase = blockIdx.x * 64;

    // load mapping
    const int lr = tid >> 2;            // 0..63 : A tile row
    const int lc = (tid & 3) * 4;       // 0,4,8,12 : A tile k offset
    const int wk = tid >> 4;            // 0..15 : W tile k row
    const int wc = (tid & 15) * 4;      // W tile col offset

    float acc[4][4];
    #pragma unroll
    for (int i = 0; i < 4; i++)
        #pragma unroll
        for (int j = 0; j < 4; j++) acc[i][j] = 0.f;

    for (int k0 = 0; k0 < K; k0 += 16) {
        float4 av = make_float4(0.f, 0.f, 0.f, 0.f);
        int ar = rowBase + lr;
        if (ar < M) av = *(const float4*)(A + (size_t)ar * K + k0 + lc);
        As[lc + 0][lr] = av.x; As[lc + 1][lr] = av.y;
        As[lc + 2][lr] = av.z; As[lc + 3][lr] = av.w;

        float4 bv = make_float4(0.f, 0.f, 0.f, 0.f);
        int bc = colBase + wc;
        if (bc < Nc) bv = *(const float4*)(W + (size_t)(k0 + wk) * Nc + bc);
        *(float4*)&Bs[wk][wc] = bv;

        __syncthreads();
        #pragma unroll
        for (int kk = 0; kk < 16; kk++) {
            float a[4], b[4];
            *(float4*)a = *(const float4*)&As[kk][ty * 4];
            *(float4*)b = *(const float4*)&Bs[kk][tx * 4];
            #pragma unroll
            for (int i = 0; i < 4; i++)
                #pragma unroll
                for (int j = 0; j < 4; j++)
                    acc[i][j] = fmaf(a[i], b[j], acc[i][j]);
        }
        __syncthreads();
    }

    #pragma unroll
    for (int i = 0; i < 4; i++) {
        int r = rowBase + ty * 4 + i;
        if (r >= M) continue;
        #pragma unroll
        for (int j = 0; j < 4; j++) {
            int c = colBase + tx * 4 + j;
            if (c < Nc) C[(size_t)r * Nc + c] = acc[i][j] + bias[c];
        }
    }
}

// ---------------- LayerNorm(128) + ELU, in place, one warp per row ----------
__global__ void ln_elu(float* __restrict__ h, const float* __restrict__ w,
                       const float* __restrict__ b, int N)
{
    int row  = blockIdx.x * (blockDim.x >> 5) + (threadIdx.x >> 5);
    int lane = threadIdx.x & 31;
    if (row >= N) return;
    float4* rp = (float4*)(h + (size_t)row * 128);
    float4 v = rp[lane];
    float s  = v.x + v.y + v.z + v.w;
    float sq = v.x * v.x + v.y * v.y + v.z * v.z + v.w * v.w;
    #pragma unroll
    for (int o = 16; o; o >>= 1) {
        s  += __shfl_xor_sync(0xffffffffu, s,  o);
        sq += __shfl_xor_sync(0xffffffffu, sq, o);
    }
    float mean = s * (1.f / 128.f);
    float var  = sq * (1.f / 128.f) - mean * mean;
    float inv  = rsqrtf(var + 1e-5f);
    float4 wv = ((const float4*)w)[lane];
    float4 bv = ((const float4*)b)[lane];
    float4 o;
    o.x = eluf((v.x - mean) * inv * wv.x + bv.x);
    o.y = eluf((v.y - mean) * inv * wv.y + bv.y);
    o.z = eluf((v.z - mean) * inv * wv.z + bv.z);
    o.w = eluf((v.w - mean) * inv * wv.w + bv.w);
    rp[lane] = o;
}

// ---------------- per-layer segment state init ------------------------------
__global__ void init_seg(float* __restrict__ m, float* __restrict__ den,
                         float* __restrict__ agg, int N)
{
    int i = blockIdx.x * blockDim.x + threadIdx.x;
    if (i < N * 4) { m[i] = -INFINITY; den[i] = 0.f; }
    if (i < N * 64) agg[i] = 0.f;
}

// ---------------- edge pass A: alpha[e,h] + segment max ---------------------
// one warp per edge; lane covers 8 consecutive floats = one head slice
__global__ void edge_alpha_max(const float* __restrict__ xl, const float* __restrict__ xr,
                               const int* __restrict__ src, const int* __restrict__ dst,
                               const float* __restrict__ att,
                               float* __restrict__ alpha, float* __restrict__ m, int E)
{
    int e    = (blockIdx.x * blockDim.x + threadIdx.x) >> 5;
    int lane = threadIdx.x & 31;
    if (e >= E) return;
    int s = src[e], d = dst[e];
    const float4* xl4 = (const float4*)(xl + (size_t)s * 256);
    const float4* xr4 = (const float4*)(xr + (size_t)d * 256);
    const float4* at4 = (const float4*)att;
    float acc = 0.f;
    #pragma unroll
    for (int j = 0; j < 2; j++) {
        int i4 = lane * 2 + j;
        float4 a = xl4[i4], b = xr4[i4], w = at4[i4];
        float t0 = a.x + b.x; t0 = t0 >= 0.f ? t0 : 0.2f * t0;
        float t1 = a.y + b.y; t1 = t1 >= 0.f ? t1 : 0.2f * t1;
        float t2 = a.z + b.z; t2 = t2 >= 0.f ? t2 : 0.2f * t2;
        float t3 = a.w + b.w; t3 = t3 >= 0.f ? t3 : 0.2f * t3;
        acc += t0 * w.x + t1 * w.y + t2 * w.z + t3 * w.w;
    }
    acc += __shfl_xor_sync(0xffffffffu, acc, 4);
    acc += __shfl_xor_sync(0xffffffffu, acc, 2);
    acc += __shfl_xor_sync(0xffffffffu, acc, 1);
    if ((lane & 7) == 0) {
        int hh = lane >> 3;
        alpha[(size_t)e * 4 + hh] = acc;
        atomicMaxF(&m[(size_t)d * 4 + hh], acc);
    }
}

// ---------------- edge pass B: denom[dst,h] += exp(alpha - m[dst]) ----------
__global__ void edge_expsum(const float* __restrict__ alpha, const int* __restrict__ dst,
                            const float* __restrict__ m, float* __restrict__ den, int E)
{
    int e = blockIdx.x * blockDim.x + threadIdx.x;
    if (e >= E) return;
    int d = dst[e];
    float4 al = ((const float4*)alpha)[e];
    float4 mm = ((const float4*)m)[d];
    atomicAdd(&den[(size_t)d * 4 + 0], __expf(al.x - mm.x));
    atomicAdd(&den[(size_t)d * 4 + 1], __expf(al.y - mm.y));
    atomicAdd(&den[(size_t)d * 4 + 2], __expf(al.z - mm.z));
    atomicAdd(&den[(size_t)d * 4 + 3], __expf(al.w - mm.w));
}

// ---------------- edge pass C: out[dst,c] += (1/4) * sum_h a[e,h]*xl[src,h,c]
// one warp per edge; lane covers head h = lane>>3, channels (lane&7)*8..+8.
// cross-head sum via shfl_xor 8/16, lanes 0..7 write 64 scalar atomics.
__global__ void edge_aggregate(const float* __restrict__ xl, const float* __restrict__ alpha,
                               const int* __restrict__ src, const int* __restrict__ dst,
                               const float* __restrict__ m, const float* __restrict__ den,
                               float* __restrict__ out, int E)
{
    int e    = (blockIdx.x * blockDim.x + threadIdx.x) >> 5;
    int lane = threadIdx.x & 31;
    if (e >= E) return;
    int s = src[e], d = dst[e];
    int h = lane >> 3;
    float a = __expf(alpha[(size_t)e * 4 + h] - m[(size_t)d * 4 + h]);
    a = a / (den[(size_t)d * 4 + h] + 1e-16f) * 0.25f;
    const float4* xl4 = (const float4*)(xl + (size_t)s * 256);
    int i4 = h * 16 + (lane & 7) * 2;
    float4 v0 = xl4[i4], v1 = xl4[i4 + 1];
    v0.x *= a; v0.y *= a; v0.z *= a; v0.w *= a;
    v1.x *= a; v1.y *= a; v1.z *= a; v1.w *= a;
    #pragma unroll
    for (int mask = 8; mask <= 16; mask <<= 1) {
        v0.x += __shfl_xor_sync(0xffffffffu, v0.x, mask);
        v0.y += __shfl_xor_sync(0xffffffffu, v0.y, mask);
        v0.z += __shfl_xor_sync(0xffffffffu, v0.z, mask);
        v0.w += __shfl_xor_sync(0xffffffffu, v0.w, mask);
        v1.x += __shfl_xor_sync(0xffffffffu, v1.x, mask);
        v1.y += __shfl_xor_sync(0xffffffffu, v1.y, mask);
        v1.z += __shfl_xor_sync(0xffffffffu, v1.z, mask);
        v1.w += __shfl_xor_sync(0xffffffffu, v1.w, mask);
    }
    if (lane < 8) {
        float* o = out + (size_t)d * 64 + lane * 8;
        atomicAdd(o + 0, v0.x); atomicAdd(o + 1, v0.y);
        atomicAdd(o + 2, v0.z); atomicAdd(o + 3, v0.w);
        atomicAdd(o + 4, v1.x); atomicAdd(o + 5, v1.y);
        atomicAdd(o + 6, v1.z); atomicAdd(o + 7, v1.w);
    }
}

// ---------------- finalize layer 1: h1 = elu(agg + bias) --------------------
__global__ void fin1(const float* __restrict__ agg, const float* __restrict__ bias,
                     float* __restrict__ h1, int N)
{
    int i = blockIdx.x * blockDim.x + threadIdx.x;
    if (i >= N * 64) return;
    h1[i] = eluf(agg[i] + bias[i & 63]);
}

// ---------------- finalize layer 2: h2 = elu(agg + bias + h1) ---------------
__global__ void fin2(const float* __restrict__ agg, const float* __restrict__ bias,
                     const float* __restrict__ h1, float* __restrict__ h2, int N)
{
    int i = blockIdx.x * blockDim.x + threadIdx.x;
    if (i >= N * 64) return;
    h2[i] = eluf(agg[i] + bias[i & 63] + h1[i]);
}

// ---------------- launch -----------------------------------------------------
extern "C" void kernel_launch(void* const* d_in, const int* in_sizes, int n_in,
                              void* d_out, int out_size)
{
    const float* x    = (const float*)d_in[0];
    const int*   ei   = (const int*)  d_in[1];
    const float* W1   = (const float*)d_in[2];
    const float* b1   = (const float*)d_in[3];
    const float* lnw  = (const float*)d_in[4];
    const float* lnb  = (const float*)d_in[5];
    const float* Wl1  = (const float*)d_in[6];
    const float* bl1  = (const float*)d_in[7];
    const float* Wr1  = (const float*)d_in[8];
    const float* br1  = (const float*)d_in[9];
    const float* att1 = (const float*)d_in[10];
    const float* bias1= (const float*)d_in[11];
    const float* Wl2  = (const float*)d_in[12];
    const float* bl2  = (const float*)d_in[13];
    const float* Wr2  = (const float*)d_in[14];
    const float* br2  = (const float*)d_in[15];
    const float* att2 = (const float*)d_in[16];
    const float* bias2= (const float*)d_in[17];
    const float* Wmu  = (const float*)d_in[18];
    const float* bmu  = (const float*)d_in[19];
    const float* Wlv  = (const float*)d_in[20];
    const float* blv  = (const float*)d_in[21];
    float* out = (float*)d_out;

    const int N = in_sizes[0] / 128;
    const int E = in_sizes[1] / 2;
    const int* src = ei;
    const int* dst = ei + E;

    float *h, *xl, *xr, *alpha, *m, *den, *agg, *h1, *h2;
    cudaGetSymbolAddress((void**)&h,     g_h);
    cudaGetSymbolAddress((void**)&xl,    g_xl);
    cudaGetSymbolAddress((void**)&xr,    g_xr);
    cudaGetSymbolAddress((void**)&alpha, g_alpha);
    cudaGetSymbolAddress((void**)&m,     g_m);
    cudaGetSymbolAddress((void**)&den,   g_den);
    cudaGetSymbolAddress((void**)&agg,   g_agg);
    cudaGetSymbolAddress((void**)&h1,    g_h1);
    cudaGetSymbolAddress((void**)&h2,    g_h2);

    const int rowBlocks = (N + 63) / 64;
    const int edgeWarpGrid = (E + 7) / 8;     // 1 warp/edge, 8 warps/block
    const int nodeGrid = (N * 64 + 255) / 256;

    // ---- stage 0: h = elu(LN(x @ W1 + b1)) ----
    sgemm_bias<<<dim3(2, rowBlocks), 256>>>(x, W1, b1, h, N, 128, 128);
    ln_elu<<<(N + 7) / 8, 256>>>(h, lnw, lnb, N);

    // ---- GATv2 layer 1 ----
    sgemm_bias<<<dim3(4, rowBlocks), 256>>>(h, Wl1, bl1, xl, N, 128, 256);
    sgemm_bias<<<dim3(4, rowBlocks), 256>>>(h, Wr1, br1, xr, N, 128, 256);
    init_seg<<<nodeGrid, 256>>>(m, den, agg, N);
    edge_alpha_max<<<edgeWarpGrid, 256>>>(xl, xr, src, dst, att1, alpha, m, E);
    edge_expsum<<<(E + 255) / 256, 256>>>(alpha, dst, m, den, E);
    edge_aggregate<<<edgeWarpGrid, 256>>>(xl, alpha, src, dst, m, den, agg, E);
    fin1<<<nodeGrid, 256>>>(agg, bias1, h1, N);

    // ---- GATv2 layer 2 (input h1 [N,64]) ----
    sgemm_bias<<<dim3(4, rowBlocks), 256>>>(h1, Wl2, bl2, xl, N, 64, 256);
    sgemm_bias<<<dim3(4, rowBlocks), 256>>>(h1, Wr2, br2, xr, N, 64, 256);
    init_seg<<<nodeGrid, 256>>>(m, den, agg, N);
    edge_alpha_max<<<edgeWarpGrid, 256>>>(xl, xr, src, dst, att2, alpha, m, E);
    edge_expsum<<<(E + 255) / 256, 256>>>(alpha, dst, m, den, E);
    edge_aggregate<<<edgeWarpGrid, 256>>>(xl, alpha, src, dst, m, den, agg, E);
    fin2<<<nodeGrid, 256>>>(agg, bias2, h1, h2, N);

    // ---- heads: mu | log_var into d_out ----
    sgemm_bias<<<dim3(1, rowBlocks), 256>>>(h2, Wmu, bmu, out,                 N, 64, 32);
    sgemm_bias<<<dim3(1, rowBlocks), 256>>>(h2, Wlv, blv, out + (size_t)N * 32, N, 64, 32);
}

// round 2
// speedup vs baseline: 1.1349x; 1.1349x over previous
#include <cuda_runtime.h>
#include <math.h>
#include <stdint.h>

#define NMAX 50176
#define EMAX 800000

// ---------------- scratch (device globals) -----------------------------------
__device__ float g_h  [NMAX * 128];
__device__ float g_xl [NMAX * 256];
__device__ float g_xr [NMAX * 256];
__device__ float g_ea [EMAX * 4];     // exp(alpha) per edge per head
__device__ float g_den[NMAX * 4];     // segment sum of exp
__device__ float g_agg[NMAX * 64];    // aggregated (head-mean folded)
__device__ float g_h1 [NMAX * 64];
__device__ float g_h2 [NMAX * 64];

// ---------------- helpers ------------------------------------------------------
__device__ __forceinline__ float eluf(float x) { return x > 0.f ? x : expm1f(x); }

__device__ __forceinline__ void red_add_v4(float* addr, float4 v) {
    asm volatile("red.global.add.v4.f32 [%0], {%1,%2,%3,%4};"
                 :: "l"(addr), "f"(v.x), "f"(v.y), "f"(v.z), "f"(v.w) : "memory");
}

// ---------------- SGEMM 128x128x8, 256 threads, 8x8 micro-tile -----------------
// C[M,Nc] = A[M,K] @ W[K,Nc] + bias.  K%8==0, Nc%128==0. Row guard on M.
__global__ void __launch_bounds__(256, 2)
sgemm128(const float* __restrict__ A, const float* __restrict__ W,
         const float* __restrict__ bias, float* __restrict__ C,
         int M, int K, int Nc)
{
    __shared__ float As[8][128];
    __shared__ float Bs[8][128];

    const int tid = threadIdx.x;
    const int tx = tid & 15;            // 0..15 col group
    const int ty = tid >> 4;            // 0..15 row group
    const int rowBase = blockIdx.y * 128;
    const int colBase = blockIdx.x * 128;

    // A loader: lr = tid&127 (conflict-free smem stores), lc = (tid>>7)*4
    const int lr = tid & 127;
    const int lc = (tid >> 7) * 4;
    // B loader
    const int wk = tid >> 5;            // 0..7
    const int wc = (tid & 31) * 4;

    const bool aok = (rowBase + lr) < M;
    const float* Arow = A + (size_t)(rowBase + lr) * K;

    float acc[8][8];
    #pragma unroll
    for (int i = 0; i < 8; i++)
        #pragma unroll
        for (int j = 0; j < 8; j++) acc[i][j] = 0.f;

    for (int k0 = 0; k0 < K; k0 += 8) {
        float4 av = make_float4(0.f, 0.f, 0.f, 0.f);
        if (aok) av = *(const float4*)(Arow + k0 + lc);
        As[lc + 0][lr] = av.x; As[lc + 1][lr] = av.y;
        As[lc + 2][lr] = av.z; As[lc + 3][lr] = av.w;

        *(float4*)&Bs[wk][wc] = *(const float4*)(W + (size_t)(k0 + wk) * Nc + colBase + wc);

        __syncthreads();
        #pragma unroll
        for (int kk = 0; kk < 8; kk++) {
            float a[8], b[8];
            *(float4*)&a[0] = *(const float4*)&As[kk][ty * 8];
            *(float4*)&a[4] = *(const float4*)&As[kk][ty * 8 + 4];
            *(float4*)&b[0] = *(const float4*)&Bs[kk][tx * 8];
            *(float4*)&b[4] = *(const float4*)&Bs[kk][tx * 8 + 4];
            #pragma unroll
            for (int i = 0; i < 8; i++)
                #pragma unroll
                for (int j = 0; j < 8; j++)
                    acc[i][j] = fmaf(a[i], b[j], acc[i][j]);
        }
        __syncthreads();
    }

    const int cbase = colBase + tx * 8;
    float4 b0 = *(const float4*)(bias + cbase);
    float4 b1 = *(const float4*)(bias + cbase + 4);
    #pragma unroll
    for (int i = 0; i < 8; i++) {
        int r = rowBase + ty * 8 + i;
        if (r >= M) continue;
        float4 o0 = make_float4(acc[i][0] + b0.x, acc[i][1] + b0.y,
                                acc[i][2] + b0.z, acc[i][3] + b0.w);
        float4 o1 = make_float4(acc[i][4] + b1.x, acc[i][5] + b1.y,
                                acc[i][6] + b1.z, acc[i][7] + b1.w);
        *(float4*)(C + (size_t)r * Nc + cbase)     = o0;
        *(float4*)(C + (size_t)r * Nc + cbase + 4) = o1;
    }
}

// ---------------- small SGEMM (64x64 tile, 4x4) for head GEMMs (Nc=32) --------
__global__ void sgemm_bias(const float* __restrict__ A, const float* __restrict__ W,
                           const float* __restrict__ bias, float* __restrict__ C,
                           int M, int K, int Nc)
{
    __shared__ float As[16][64];
    __shared__ float Bs[16][64];
    const int tid = threadIdx.x;
    const int tx = tid & 15, ty = tid >> 4;
    const int rowBase = blockIdx.y * 64;
    const int colBase = blockIdx.x * 64;
    const int lr = tid >> 2, lc = (tid & 3) * 4;
    const int wk = tid >> 4, wc = (tid & 15) * 4;

    float acc[4][4];
    #pragma unroll
    for (int i = 0; i < 4; i++)
        #pragma unroll
        for (int j = 0; j < 4; j++) acc[i][j] = 0.f;

    for (int k0 = 0; k0 < K; k0 += 16) {
        float4 av = make_float4(0.f, 0.f, 0.f, 0.f);
        int ar = rowBase + lr;
        if (ar < M) av = *(const float4*)(A + (size_t)ar * K + k0 + lc);
        As[lc + 0][lr] = av.x; As[lc + 1][lr] = av.y;
        As[lc + 2][lr] = av.z; As[lc + 3][lr] = av.w;
        float4 bv = make_float4(0.f, 0.f, 0.f, 0.f);
        int bc = colBase + wc;
        if (bc < Nc) bv = *(const float4*)(W + (size_t)(k0 + wk) * Nc + bc);
        *(float4*)&Bs[wk][wc] = bv;
        __syncthreads();
        #pragma unroll
        for (int kk = 0; kk < 16; kk++) {
            float a[4], b[4];
            *(float4*)a = *(const float4*)&As[kk][ty * 4];
            *(float4*)b = *(const float4*)&Bs[kk][tx * 4];
            #pragma unroll
            for (int i = 0; i < 4; i++)
                #pragma unroll
                for (int j = 0; j < 4; j++)
                    acc[i][j] = fmaf(a[i], b[j], acc[i][j]);
        }
        __syncthreads();
    }
    #pragma unroll
    for (int i = 0; i < 4; i++) {
        int r = rowBase + ty * 4 + i;
        if (r >= M) continue;
        #pragma unroll
        for (int j = 0; j < 4; j++) {
            int c = colBase + tx * 4 + j;
            if (c < Nc) C[(size_t)r * Nc + c] = acc[i][j] + bias[c];
        }
    }
}

// ---------------- LayerNorm(128) + ELU ----------------------------------------
__global__ void ln_elu(float* __restrict__ h, const float* __restrict__ w,
                       const float* __restrict__ b, int N)
{
    int row  = blockIdx.x * (blockDim.x >> 5) + (threadIdx.x >> 5);
    int lane = threadIdx.x & 31;
    if (row >= N) return;
    float4* rp = (float4*)(h + (size_t)row * 128);
    float4 v = rp[lane];
    float s  = v.x + v.y + v.z + v.w;
    float sq = v.x * v.x + v.y * v.y + v.z * v.z + v.w * v.w;
    #pragma unroll
    for (int o = 16; o; o >>= 1) {
        s  += __shfl_xor_sync(0xffffffffu, s,  o);
        sq += __shfl_xor_sync(0xffffffffu, sq, o);
    }
    float mean = s * (1.f / 128.f);
    float var  = sq * (1.f / 128.f) - mean * mean;
    float inv  = rsqrtf(var + 1e-5f);
    float4 wv = ((const float4*)w)[lane];
    float4 bv = ((const float4*)b)[lane];
    float4 o;
    o.x = eluf((v.x - mean) * inv * wv.x + bv.x);
    o.y = eluf((v.y - mean) * inv * wv.y + bv.y);
    o.z = eluf((v.z - mean) * inv * wv.z + bv.z);
    o.w = eluf((v.w - mean) * inv * wv.w + bv.w);
    rp[lane] = o;
}

// ---------------- zero den + agg ------------------------------------------------
__global__ void init_seg(float* __restrict__ den, float* __restrict__ agg, int N)
{
    int i = blockIdx.x * blockDim.x + threadIdx.x;
    if (i < N * 4)  den[i] = 0.f;
    if (i < N * 64) agg[i] = 0.f;
}

// ---------------- edge pass A: ea[e,h] = exp(alpha); den[dst,h] += ea ----------
// one warp per edge; lanes in groups of 8 cover one head slice.
__global__ void edge_alpha_den(const float* __restrict__ xl, const float* __restrict__ xr,
                               const int* __restrict__ src, const int* __restrict__ dst,
                               const float* __restrict__ att,
                               float* __restrict__ ea, float* __restrict__ den, int E)
{
    int e    = (blockIdx.x * blockDim.x + threadIdx.x) >> 5;
    int lane = threadIdx.x & 31;
    if (e >= E) return;
    int s = src[e], d = dst[e];
    const float4* xl4 = (const float4*)(xl + (size_t)s * 256);
    const float4* xr4 = (const float4*)(xr + (size_t)d * 256);
    const float4* at4 = (const float4*)att;
    float acc = 0.f;
    #pragma unroll
    for (int j = 0; j < 2; j++) {
        int i4 = lane * 2 + j;
        float4 a = xl4[i4], b = xr4[i4], w = at4[i4];
        float t0 = a.x + b.x; t0 = t0 >= 0.f ? t0 : 0.2f * t0;
        float t1 = a.y + b.y; t1 = t1 >= 0.f ? t1 : 0.2f * t1;
        float t2 = a.z + b.z; t2 = t2 >= 0.f ? t2 : 0.2f * t2;
        float t3 = a.w + b.w; t3 = t3 >= 0.f ? t3 : 0.2f * t3;
        acc += t0 * w.x + t1 * w.y + t2 * w.z + t3 * w.w;
    }
    acc += __shfl_xor_sync(0xffffffffu, acc, 4);
    acc += __shfl_xor_sync(0xffffffffu, acc, 2);
    acc += __shfl_xor_sync(0xffffffffu, acc, 1);
    // every lane in group h=lane>>3 now holds alpha_h; redistribute: lane i gets head (i&3)
    float aH = __shfl_sync(0xffffffffu, acc, (lane & 3) << 3);
    float v  = __expf(aH);
    float v1 = __shfl_sync(0xffffffffu, v, 1);
    float v2 = __shfl_sync(0xffffffffu, v, 2);
    float v3 = __shfl_sync(0xffffffffu, v, 3);
    if (lane == 0) {
        float4 q = make_float4(v, v1, v2, v3);
        *(float4*)(ea + (size_t)e * 4) = q;
        red_add_v4(den + (size_t)d * 4, q);
    }
}

// ---------------- edge pass B: out[dst] += (1/4) sum_h (ea/den) * xl[src,h,:] --
__global__ void edge_aggregate(const float* __restrict__ xl, const float* __restrict__ ea,
                               const int* __restrict__ src, const int* __restrict__ dst,
                               const float* __restrict__ den,
                               float* __restrict__ out, int E)
{
    int e    = (blockIdx.x * blockDim.x + threadIdx.x) >> 5;
    int lane = threadIdx.x & 31;
    if (e >= E) return;
    int s = src[e], d = dst[e];
    int h = lane >> 3;
    float4 dn = __ldg((const float4*)den + d);
    float dh = (h == 0) ? dn.x : (h == 1) ? dn.y : (h == 2) ? dn.z : dn.w;
    float a = __ldg(ea + (size_t)e * 4 + h) / (dh + 1e-16f) * 0.25f;
    const float4* xl4 = (const float4*)(xl + (size_t)s * 256);
    int i4 = h * 16 + (lane & 7) * 2;
    float4 v0 = xl4[i4], v1 = xl4[i4 + 1];
    v0.x *= a; v0.y *= a; v0.z *= a; v0.w *= a;
    v1.x *= a; v1.y *= a; v1.z *= a; v1.w *= a;
    #pragma unroll
    for (int mask = 8; mask <= 16; mask <<= 1) {
        v0.x += __shfl_xor_sync(0xffffffffu, v0.x, mask);
        v0.y += __shfl_xor_sync(0xffffffffu, v0.y, mask);
        v0.z += __shfl_xor_sync(0xffffffffu, v0.z, mask);
        v0.w += __shfl_xor_sync(0xffffffffu, v0.w, mask);
        v1.x += __shfl_xor_sync(0xffffffffu, v1.x, mask);
        v1.y += __shfl_xor_sync(0xffffffffu, v1.y, mask);
        v1.z += __shfl_xor_sync(0xffffffffu, v1.z, mask);
        v1.w += __shfl_xor_sync(0xffffffffu, v1.w, mask);
    }
    if (lane < 8) {
        float* o = out + (size_t)d * 64 + lane * 8;
        red_add_v4(o,     v0);
        red_add_v4(o + 4, v1);
    }
}

// ---------------- finalize -----------------------------------------------------
__global__ void fin1(const float4* __restrict__ agg, const float* __restrict__ bias,
                     float4* __restrict__ h1, int N)
{
    int i = blockIdx.x * blockDim.x + threadIdx.x;
    if (i >= N * 16) return;
    float4 v = agg[i];
    const float4 b = ((const float4*)bias)[i & 15];
    float4 o;
    o.x = eluf(v.x + b.x); o.y = eluf(v.y + b.y);
    o.z = eluf(v.z + b.z); o.w = eluf(v.w + b.w);
    h1[i] = o;
}

__global__ void fin2(const float4* __restrict__ agg, const float* __restrict__ bias,
                     const float4* __restrict__ h1, float4* __restrict__ h2, int N)
{
    int i = blockIdx.x * blockDim.x + threadIdx.x;
    if (i >= N * 16) return;
    float4 v = agg[i];
    float4 r = h1[i];
    const float4 b = ((const float4*)bias)[i & 15];
    float4 o;
    o.x = eluf(v.x + b.x + r.x); o.y = eluf(v.y + b.y + r.y);
    o.z = eluf(v.z + b.z + r.z); o.w = eluf(v.w + b.w + r.w);
    h2[i] = o;
}

// ---------------- launch ---------------------------------------------------------
extern "C" void kernel_launch(void* const* d_in, const int* in_sizes, int n_in,
                              void* d_out, int out_size)
{
    const float* x    = (const float*)d_in[0];
    const int*   ei   = (const int*)  d_in[1];
    const float* W1   = (const float*)d_in[2];
    const float* b1   = (const float*)d_in[3];
    const float* lnw  = (const float*)d_in[4];
    const float* lnb  = (const float*)d_in[5];
    const float* Wl1  = (const float*)d_in[6];
    const float* bl1  = (const float*)d_in[7];
    const float* Wr1  = (const float*)d_in[8];
    const float* br1  = (const float*)d_in[9];
    const float* att1 = (const float*)d_in[10];
    const float* bias1= (const float*)d_in[11];
    const float* Wl2  = (const float*)d_in[12];
    const float* bl2  = (const float*)d_in[13];
    const float* Wr2  = (const float*)d_in[14];
    const float* br2  = (const float*)d_in[15];
    const float* att2 = (const float*)d_in[16];
    const float* bias2= (const float*)d_in[17];
    const float* Wmu  = (const float*)d_in[18];
    const float* bmu  = (const float*)d_in[19];
    const float* Wlv  = (const float*)d_in[20];
    const float* blv  = (const float*)d_in[21];
    float* out = (float*)d_out;

    const int N = in_sizes[0] / 128;
    const int E = in_sizes[1] / 2;
    const int* src = ei;
    const int* dst = ei + E;

    float *h, *xl, *xr, *ea, *den, *agg, *h1, *h2;
    cudaGetSymbolAddress((void**)&h,   g_h);
    cudaGetSymbolAddress((void**)&xl,  g_xl);
    cudaGetSymbolAddress((void**)&xr,  g_xr);
    cudaGetSymbolAddress((void**)&ea,  g_ea);
    cudaGetSymbolAddress((void**)&den, g_den);
    cudaGetSymbolAddress((void**)&agg, g_agg);
    cudaGetSymbolAddress((void**)&h1,  g_h1);
    cudaGetSymbolAddress((void**)&h2,  g_h2);

    const int rb128 = (N + 127) / 128;
    const int rb64  = (N + 63) / 64;
    const int edgeWarpGrid = (E + 7) / 8;
    const int nodeGrid = (N * 64 + 255) / 256;
    const int finGrid  = (N * 16 + 255) / 256;

    // stage 0: h = elu(LN(x @ W1 + b1))
    sgemm128<<<dim3(1, rb128), 256>>>(x, W1, b1, h, N, 128, 128);
    ln_elu<<<(N + 7) / 8, 256>>>(h, lnw, lnb, N);

    // GATv2 layer 1
    sgemm128<<<dim3(2, rb128), 256>>>(h, Wl1, bl1, xl, N, 128, 256);
    sgemm128<<<dim3(2, rb128), 256>>>(h, Wr1, br1, xr, N, 128, 256);
    init_seg<<<nodeGrid, 256>>>(den, agg, N);
    edge_alpha_den<<<edgeWarpGrid, 256>>>(xl, xr, src, dst, att1, ea, den, E);
    edge_aggregate<<<edgeWarpGrid, 256>>>(xl, ea, src, dst, den, agg, E);
    fin1<<<finGrid, 256>>>((const float4*)agg, bias1, (float4*)h1, N);

    // GATv2 layer 2
    sgemm128<<<dim3(2, rb128), 256>>>(h1, Wl2, bl2, xl, N, 64, 256);
    sgemm128<<<dim3(2, rb128), 256>>>(h1, Wr2, br2, xr, N, 64, 256);
    init_seg<<<nodeGrid, 256>>>(den, agg, N);
    edge_alpha_den<<<edgeWarpGrid, 256>>>(xl, xr, src, dst, att2, ea, den, E);
    edge_aggregate<<<edgeWarpGrid, 256>>>(xl, ea, src, dst, den, agg, E);
    fin2<<<finGrid, 256>>>((const float4*)agg, bias2, (const float4*)h1, (float4*)h2, N);

    // heads
    sgemm_bias<<<dim3(1, rb64), 256>>>(h2, Wmu, bmu, out,                  N, 64, 32);
    sgemm_bias<<<dim3(1, rb64), 256>>>(h2, Wlv, blv, out + (size_t)N * 32, N, 64, 32);
}

// round 3
// speedup vs baseline: 1.7043x; 1.5017x over previous
#include <cuda_runtime.h>
#include <math.h>
#include <stdint.h>

#define NMAX 50176
#define EMAX 800000

// ---------------- scratch (device globals) -----------------------------------
__device__ float g_h  [NMAX * 128];
__device__ float g_xl [NMAX * 256];
__device__ float g_xr [NMAX * 256];
__device__ float g_ea [EMAX * 4];
__device__ float g_h1 [NMAX * 64];
__device__ float g_h2 [NMAX * 64];
__device__ int   g_cnt   [NMAX];
__device__ int   g_rowptr[NMAX];
__device__ int   g_woff  [NMAX];
__device__ int   g_part  [256];
__device__ int   g_csrsrc[EMAX];

__device__ __forceinline__ float eluf(float x) { return x > 0.f ? x : expm1f(x); }

// ================= CSR build ====================================================
__global__ void csr_zero(int* __restrict__ cnt, int N)
{
    int i = blockIdx.x * blockDim.x + threadIdx.x;
    if (i < N) cnt[i] = 0;
}
__global__ void csr_count(const int* __restrict__ dst, int* __restrict__ cnt, int E)
{
    int i = blockIdx.x * blockDim.x + threadIdx.x;
    if (i < E) atomicAdd(&cnt[dst[i]], 1);
}
__global__ void scan1(const int* __restrict__ cnt, int* __restrict__ rowptr,
                      int* __restrict__ part, int N)
{
    __shared__ int sh[256];
    int tid = threadIdx.x;
    int i = blockIdx.x * 256 + tid;
    int v = (i < N) ? cnt[i] : 0;
    sh[tid] = v; __syncthreads();
    #pragma unroll
    for (int o = 1; o < 256; o <<= 1) {
        int t = (tid >= o) ? sh[tid - o] : 0;
        __syncthreads();
        sh[tid] += t;
        __syncthreads();
    }
    if (i < N) rowptr[i] = sh[tid] - v;
    if (tid == 255) part[blockIdx.x] = sh[255];
}
__global__ void scan2(int* __restrict__ part, int NB)
{
    __shared__ int sh[256];
    int tid = threadIdx.x;
    int v = (tid < NB) ? part[tid] : 0;
    sh[tid] = v; __syncthreads();
    #pragma unroll
    for (int o = 1; o < 256; o <<= 1) {
        int t = (tid >= o) ? sh[tid - o] : 0;
        __syncthreads();
        sh[tid] += t;
        __syncthreads();
    }
    if (tid < NB) part[tid] = sh[tid] - v;
}
__global__ void scan3(int* __restrict__ rowptr, const int* __restrict__ part,
                      int* __restrict__ woff, int N)
{
    int i = blockIdx.x * blockDim.x + threadIdx.x;
    if (i < N) {
        int r = rowptr[i] + part[i >> 8];
        rowptr[i] = r;
        woff[i] = r;
    }
}
__global__ void csr_scatter(const int* __restrict__ src, const int* __restrict__ dst,
                            int* __restrict__ woff, int* __restrict__ csrsrc, int E)
{
    int e = blockIdx.x * blockDim.x + threadIdx.x;
    if (e < E) {
        int p = atomicAdd(&woff[dst[e]], 1);
        csrsrc[p] = src[e];
    }
}

// ================= double-buffered SGEMM 128x128, BK=16, 8x8 micro-tile ========
__global__ void __launch_bounds__(256, 2)
sgemm128(const float* __restrict__ A, const float* __restrict__ W,
         const float* __restrict__ bias, float* __restrict__ C,
         int M, int K, int Nc)
{
    __shared__ float As[2][16][128];
    __shared__ float Bs[2][16][128];

    const int tid = threadIdx.x;
    const int tx = tid & 15;
    const int ty = tid >> 4;
    const int rowBase = blockIdx.y * 128;
    const int colBase = blockIdx.x * 128;

    const int lr = tid & 127;
    const int lc = (tid >> 7) * 4;        // 0 or 4; +8 for second quad
    const int wk = tid >> 5;              // 0..7; +8 for second row
    const int wc = (tid & 31) * 4;

    const bool aok = (rowBase + lr) < M;
    const float* Arow = A + (size_t)(rowBase + lr) * K;
    const float* Wp = W + colBase + wc;

    const float4 z4 = make_float4(0.f, 0.f, 0.f, 0.f);
    float4 av0 = aok ? *(const float4*)(Arow + lc)     : z4;
    float4 av1 = aok ? *(const float4*)(Arow + lc + 8) : z4;
    float4 bv0 = *(const float4*)(Wp + (size_t)wk * Nc);
    float4 bv1 = *(const float4*)(Wp + (size_t)(wk + 8) * Nc);

    As[0][lc + 0][lr] = av0.x; As[0][lc + 1][lr] = av0.y;
    As[0][lc + 2][lr] = av0.z; As[0][lc + 3][lr] = av0.w;
    As[0][lc + 8][lr] = av1.x; As[0][lc + 9][lr] = av1.y;
    As[0][lc +10][lr] = av1.z; As[0][lc +11][lr] = av1.w;
    *(float4*)&Bs[0][wk][wc]     = bv0;
    *(float4*)&Bs[0][wk + 8][wc] = bv1;
    __syncthreads();

    float acc[8][8];
    #pragma unroll
    for (int i = 0; i < 8; i++)
        #pragma unroll
        for (int j = 0; j < 8; j++) acc[i][j] = 0.f;

    const int T = K >> 4;
    for (int t = 0; t < T; t++) {
        const int buf = t & 1;
        if (t + 1 < T) {
            const int k0 = (t + 1) << 4;
            av0 = aok ? *(const float4*)(Arow + k0 + lc)     : z4;
            av1 = aok ? *(const float4*)(Arow + k0 + lc + 8) : z4;
            bv0 = *(const float4*)(Wp + (size_t)(k0 + wk) * Nc);
            bv1 = *(const float4*)(Wp + (size_t)(k0 + wk + 8) * Nc);
        }
        #pragma unroll
        for (int kk = 0; kk < 16; kk++) {
            float a[8], b[8];
            *(float4*)&a[0] = *(const float4*)&As[buf][kk][ty * 8];
            *(float4*)&a[4] = *(const float4*)&As[buf][kk][ty * 8 + 4];
            *(float4*)&b[0] = *(const float4*)&Bs[buf][kk][tx * 8];
            *(float4*)&b[4] = *(const float4*)&Bs[buf][kk][tx * 8 + 4];
            #pragma unroll
            for (int i = 0; i < 8; i++)
                #pragma unroll
                for (int j = 0; j < 8; j++)
                    acc[i][j] = fmaf(a[i], b[j], acc[i][j]);
        }
        if (t + 1 < T) {
            const int nb = buf ^ 1;
            As[nb][lc + 0][lr] = av0.x; As[nb][lc + 1][lr] = av0.y;
            As[nb][lc + 2][lr] = av0.z; As[nb][lc + 3][lr] = av0.w;
            As[nb][lc + 8][lr] = av1.x; As[nb][lc + 9][lr] = av1.y;
            As[nb][lc +10][lr] = av1.z; As[nb][lc +11][lr] = av1.w;
            *(float4*)&Bs[nb][wk][wc]     = bv0;
            *(float4*)&Bs[nb][wk + 8][wc] = bv1;
            __syncthreads();
        }
    }

    const int cbase = colBase + tx * 8;
    float4 b0 = *(const float4*)(bias + cbase);
    float4 b1 = *(const float4*)(bias + cbase + 4);
    #pragma unroll
    for (int i = 0; i < 8; i++) {
        int r = rowBase + ty * 8 + i;
        if (r >= M) continue;
        float4 o0 = make_float4(acc[i][0] + b0.x, acc[i][1] + b0.y,
                                acc[i][2] + b0.z, acc[i][3] + b0.w);
        float4 o1 = make_float4(acc[i][4] + b1.x, acc[i][5] + b1.y,
                                acc[i][6] + b1.z, acc[i][7] + b1.w);
        *(float4*)(C + (size_t)r * Nc + cbase)     = o0;
        *(float4*)(C + (size_t)r * Nc + cbase + 4) = o1;
    }
}

// ================= small SGEMM for head GEMMs (Nc=32) ==========================
__global__ void sgemm_bias(const float* __restrict__ A, const float* __restrict__ W,
                           const float* __restrict__ bias, float* __restrict__ C,
                           int M, int K, int Nc)
{
    __shared__ float As[16][64];
    __shared__ float Bs[16][64];
    const int tid = threadIdx.x;
    const int tx = tid & 15, ty = tid >> 4;
    const int rowBase = blockIdx.y * 64;
    const int colBase = blockIdx.x * 64;
    const int lr = tid >> 2, lc = (tid & 3) * 4;
    const int wk = tid >> 4, wc = (tid & 15) * 4;

    float acc[4][4];
    #pragma unroll
    for (int i = 0; i < 4; i++)
        #pragma unroll
        for (int j = 0; j < 4; j++) acc[i][j] = 0.f;

    for (int k0 = 0; k0 < K; k0 += 16) {
        float4 av = make_float4(0.f, 0.f, 0.f, 0.f);
        int ar = rowBase + lr;
        if (ar < M) av = *(const float4*)(A + (size_t)ar * K + k0 + lc);
        As[lc + 0][lr] = av.x; As[lc + 1][lr] = av.y;
        As[lc + 2][lr] = av.z; As[lc + 3][lr] = av.w;
        float4 bv = make_float4(0.f, 0.f, 0.f, 0.f);
        int bc = colBase + wc;
        if (bc < Nc) bv = *(const float4*)(W + (size_t)(k0 + wk) * Nc + bc);
        *(float4*)&Bs[wk][wc] = bv;
        __syncthreads();
        #pragma unroll
        for (int kk = 0; kk < 16; kk++) {
            float a[4], b[4];
            *(float4*)a = *(const float4*)&As[kk][ty * 4];
            *(float4*)b = *(const float4*)&Bs[kk][tx * 4];
            #pragma unroll
            for (int i = 0; i < 4; i++)
                #pragma unroll
                for (int j = 0; j < 4; j++)
                    acc[i][j] = fmaf(a[i], b[j], acc[i][j]);
        }
        __syncthreads();
    }
    #pragma unroll
    for (int i = 0; i < 4; i++) {
        int r = rowBase + ty * 4 + i;
        if (r >= M) continue;
        #pragma unroll
        for (int j = 0; j < 4; j++) {
            int c = colBase + tx * 4 + j;
            if (c < Nc) C[(size_t)r * Nc + c] = acc[i][j] + bias[c];
        }
    }
}

// ================= LayerNorm(128) + ELU =========================================
__global__ void ln_elu(float* __restrict__ h, const float* __restrict__ w,
                       const float* __restrict__ b, int N)
{
    int row  = blockIdx.x * (blockDim.x >> 5) + (threadIdx.x >> 5);
    int lane = threadIdx.x & 31;
    if (row >= N) return;
    float4* rp = (float4*)(h + (size_t)row * 128);
    float4 v = rp[lane];
    float s  = v.x + v.y + v.z + v.w;
    float sq = v.x * v.x + v.y * v.y + v.z * v.z + v.w * v.w;
    #pragma unroll
    for (int o = 16; o; o >>= 1) {
        s  += __shfl_xor_sync(0xffffffffu, s,  o);
        sq += __shfl_xor_sync(0xffffffffu, sq, o);
    }
    float mean = s * (1.f / 128.f);
    float var  = sq * (1.f / 128.f) - mean * mean;
    float inv  = rsqrtf(var + 1e-5f);
    float4 wv = ((const float4*)w)[lane];
    float4 bv = ((const float4*)b)[lane];
    float4 o;
    o.x = eluf((v.x - mean) * inv * wv.x + bv.x);
    o.y = eluf((v.y - mean) * inv * wv.y + bv.y);
    o.z = eluf((v.z - mean) * inv * wv.z + bv.z);
    o.w = eluf((v.w - mean) * inv * wv.w + bv.w);
    rp[lane] = o;
}

// ================= fused node-major GATv2 pass ==================================
// One warp per destination node. Loop1: alpha -> exp -> den (regs) + ea[slot].
// Loop2: out[c] = elu( (1/4) sum_h sum_e (ea/den) xl[src,h,c] + bias[c] (+resid) ).
__global__ void gat_node(const float* __restrict__ xl, const float* __restrict__ xr,
                         const int* __restrict__ rowptr, const int* __restrict__ cnt,
                         const int* __restrict__ csrsrc, const float* __restrict__ att,
                         float* __restrict__ ea, const float* __restrict__ bias,
                         const float* __restrict__ resid, float* __restrict__ out, int N)
{
    int node = (blockIdx.x * blockDim.x + threadIdx.x) >> 5;
    int lane = threadIdx.x & 31;
    if (node >= N) return;
    const int start = rowptr[node];
    const int deg   = cnt[node];

    const float4* at4 = (const float4*)att;
    const float4* xr4 = (const float4*)(xr + (size_t)node * 256);
    const int i4a = lane * 2;
    const float4 w0 = at4[i4a], w1 = at4[i4a + 1];
    const float4 r0 = xr4[i4a], r1 = xr4[i4a + 1];

    // ---- loop 1: ea + denominator ----
    float den = 0.f;   // per lane: denominator of head (lane & 3)
    for (int i0 = 0; i0 < deg; i0 += 32) {
        int nn = min(32, deg - i0);
        int sReg = (lane < nn) ? csrsrc[start + i0 + lane] : 0;
        for (int i = 0; i < nn; i++) {
            int sv = __shfl_sync(0xffffffffu, sReg, i);
            const float4* xl4 = (const float4*)(xl + (size_t)sv * 256);
            float4 a0 = xl4[i4a], a1 = xl4[i4a + 1];
            float t, acc = 0.f;
            t = a0.x + r0.x; t = t >= 0.f ? t : 0.2f * t; acc += t * w0.x;
            t = a0.y + r0.y; t = t >= 0.f ? t : 0.2f * t; acc += t * w0.y;
            t = a0.z + r0.z; t = t >= 0.f ? t : 0.2f * t; acc += t * w0.z;
            t = a0.w + r0.w; t = t >= 0.f ? t : 0.2f * t; acc += t * w0.w;
            t = a1.x + r1.x; t = t >= 0.f ? t : 0.2f * t; acc += t * w1.x;
            t = a1.y + r1.y; t = t >= 0.f ? t : 0.2f * t; acc += t * w1.y;
            t = a1.z + r1.z; t = t >= 0.f ? t : 0.2f * t; acc += t * w1.z;
            t = a1.w + r1.w; t = t >= 0.f ? t : 0.2f * t; acc += t * w1.w;
            acc += __shfl_xor_sync(0xffffffffu, acc, 4);
            acc += __shfl_xor_sync(0xffffffffu, acc, 2);
            acc += __shfl_xor_sync(0xffffffffu, acc, 1);
            float aH = __shfl_sync(0xffffffffu, acc, (lane & 3) << 3);
            float v  = __expf(aH);
            den += v;
            float v1 = __shfl_sync(0xffffffffu, v, 1);
            float v2 = __shfl_sync(0xffffffffu, v, 2);
            float v3 = __shfl_sync(0xffffffffu, v, 3);
            if (lane == 0)
                *(float4*)(ea + (size_t)(start + i0 + i) * 4) = make_float4(v, v1, v2, v3);
        }
    }
    float d0 = __shfl_sync(0xffffffffu, den, 0);
    float d1 = __shfl_sync(0xffffffffu, den, 1);
    float d2 = __shfl_sync(0xffffffffu, den, 2);
    float d3 = __shfl_sync(0xffffffffu, den, 3);
    const float4 idn = make_float4(0.25f / (d0 + 1e-16f), 0.25f / (d1 + 1e-16f),
                                   0.25f / (d2 + 1e-16f), 0.25f / (d3 + 1e-16f));

    // ---- loop 2: aggregate ----
    const int c0 = lane * 2;
    float ax = 0.f, ay = 0.f;
    for (int i0 = 0; i0 < deg; i0 += 32) {
        int nn = min(32, deg - i0);
        int sReg = (lane < nn) ? csrsrc[start + i0 + lane] : 0;
        for (int i = 0; i < nn; i++) {
            int sv = __shfl_sync(0xffffffffu, sReg, i);
            float4 av = *(const float4*)(ea + (size_t)(start + i0 + i) * 4);
            av.x *= idn.x; av.y *= idn.y; av.z *= idn.z; av.w *= idn.w;
            const float* xs = xl + (size_t)sv * 256 + c0;
            float2 x0 = *(const float2*)(xs);
            float2 x1 = *(const float2*)(xs + 64);
            float2 x2 = *(const float2*)(xs + 128);
            float2 x3 = *(const float2*)(xs + 192);
            ax += av.x * x0.x + av.y * x1.x + av.z * x2.x + av.w * x3.x;
            ay += av.x * x0.y + av.y * x1.y + av.z * x2.y + av.w * x3.y;
        }
    }

    float2 b = *(const float2*)(bias + c0);
    float rx = 0.f, ry = 0.f;
    if (resid) {
        float2 rv = *(const float2*)(resid + (size_t)node * 64 + c0);
        rx = rv.x; ry = rv.y;
    }
    float2 o;
    o.x = eluf(ax + b.x + rx);
    o.y = eluf(ay + b.y + ry);
    *(float2*)(out + (size_t)node * 64 + c0) = o;
}

// ================= launch ========================================================
extern "C" void kernel_launch(void* const* d_in, const int* in_sizes, int n_in,
                              void* d_out, int out_size)
{
    const float* x    = (const float*)d_in[0];
    const int*   ei   = (const int*)  d_in[1];
    const float* W1   = (const float*)d_in[2];
    const float* b1   = (const float*)d_in[3];
    const float* lnw  = (const float*)d_in[4];
    const float* lnb  = (const float*)d_in[5];
    const float* Wl1  = (const float*)d_in[6];
    const float* bl1  = (const float*)d_in[7];
    const float* Wr1  = (const float*)d_in[8];
    const float* br1  = (const float*)d_in[9];
    const float* att1 = (const float*)d_in[10];
    const float* bias1= (const float*)d_in[11];
    const float* Wl2  = (const float*)d_in[12];
    const float* bl2  = (const float*)d_in[13];
    const float* Wr2  = (const float*)d_in[14];
    const float* br2  = (const float*)d_in[15];
    const float* att2 = (const float*)d_in[16];
    const float* bias2= (const float*)d_in[17];
    const float* Wmu  = (const float*)d_in[18];
    const float* bmu  = (const float*)d_in[19];
    const float* Wlv  = (const float*)d_in[20];
    const float* blv  = (const float*)d_in[21];
    float* out = (float*)d_out;

    const int N = in_sizes[0] / 128;
    const int E = in_sizes[1] / 2;
    const int* src = ei;
    const int* dst = ei + E;

    float *h, *xl, *xr, *ea, *h1, *h2;
    int *cnt, *rowptr, *woff, *part, *csrsrc;
    cudaGetSymbolAddress((void**)&h,      g_h);
    cudaGetSymbolAddress((void**)&xl,     g_xl);
    cudaGetSymbolAddress((void**)&xr,     g_xr);
    cudaGetSymbolAddress((void**)&ea,     g_ea);
    cudaGetSymbolAddress((void**)&h1,     g_h1);
    cudaGetSymbolAddress((void**)&h2,     g_h2);
    cudaGetSymbolAddress((void**)&cnt,    g_cnt);
    cudaGetSymbolAddress((void**)&rowptr, g_rowptr);
    cudaGetSymbolAddress((void**)&woff,   g_woff);
    cudaGetSymbolAddress((void**)&part,   g_part);
    cudaGetSymbolAddress((void**)&csrsrc, g_csrsrc);

    const int rb128 = (N + 127) / 128;
    const int rb64  = (N + 63) / 64;
    const int NB    = (N + 255) / 256;
    const int nodeWarpGrid = (N + 7) / 8;      // 8 warps / block

    // ---- CSR build (edge structure shared by both layers) ----
    csr_zero   <<<NB, 256>>>(cnt, N);
    csr_count  <<<(E + 255) / 256, 256>>>(dst, cnt, E);
    scan1      <<<NB, 256>>>(cnt, rowptr, part, N);
    scan2      <<<1, 256>>>(part, NB);
    scan3      <<<NB, 256>>>(rowptr, part, woff, N);
    csr_scatter<<<(E + 255) / 256, 256>>>(src, dst, woff, csrsrc, E);

    // ---- stage 0: h = elu(LN(x @ W1 + b1)) ----
    sgemm128<<<dim3(1, rb128), 256>>>(x, W1, b1, h, N, 128, 128);
    ln_elu<<<(N + 7) / 8, 256>>>(h, lnw, lnb, N);

    // ---- GATv2 layer 1 ----
    sgemm128<<<dim3(2, rb128), 256>>>(h, Wl1, bl1, xl, N, 128, 256);
    sgemm128<<<dim3(2, rb128), 256>>>(h, Wr1, br1, xr, N, 128, 256);
    gat_node<<<nodeWarpGrid, 256>>>(xl, xr, rowptr, cnt, csrsrc, att1, ea,
                                    bias1, nullptr, h1, N);

    // ---- GATv2 layer 2 ----
    sgemm128<<<dim3(2, rb128), 256>>>(h1, Wl2, bl2, xl, N, 64, 256);
    sgemm128<<<dim3(2, rb128), 256>>>(h1, Wr2, br2, xr, N, 64, 256);
    gat_node<<<nodeWarpGrid, 256>>>(xl, xr, rowptr, cnt, csrsrc, att2, ea,
                                    bias2, h1, h2, N);

    // ---- heads ----
    sgemm_bias<<<dim3(1, rb64), 256>>>(h2, Wmu, bmu, out,                  N, 64, 32);
    sgemm_bias<<<dim3(1, rb64), 256>>>(h2, Wlv, blv, out + (size_t)N * 32, N, 64, 32);
}

// round 4
// speedup vs baseline: 1.9071x; 1.1189x over previous
#include <cuda_runtime.h>
#include <math.h>
#include <stdint.h>

#define NMAX 50176
#define EMAX 800000

// ---------------- scratch (device globals) -----------------------------------
__device__ float g_h  [NMAX * 128];
__device__ float g_xl [NMAX * 256];
__device__ float g_xr [NMAX * 256];
__device__ float g_h1 [NMAX * 64];
__device__ float g_h2 [NMAX * 64];
__device__ int   g_cnt   [NMAX];
__device__ int   g_rowptr[NMAX];
__device__ int   g_woff  [NMAX];
__device__ int   g_part  [256];
__device__ int   g_csrsrc[EMAX];

__device__ __forceinline__ float eluf(float x) { return x > 0.f ? x : expm1f(x); }

// ================= CSR build ====================================================
__global__ void csr_zero(int* __restrict__ cnt, int N)
{
    int i = blockIdx.x * blockDim.x + threadIdx.x;
    if (i < N) cnt[i] = 0;
}
__global__ void csr_count(const int* __restrict__ dst, int* __restrict__ cnt, int E)
{
    int i = blockIdx.x * blockDim.x + threadIdx.x;
    if (i < E) atomicAdd(&cnt[dst[i]], 1);
}
__global__ void scan1(const int* __restrict__ cnt, int* __restrict__ rowptr,
                      int* __restrict__ part, int N)
{
    __shared__ int sh[256];
    int tid = threadIdx.x;
    int i = blockIdx.x * 256 + tid;
    int v = (i < N) ? cnt[i] : 0;
    sh[tid] = v; __syncthreads();
    #pragma unroll
    for (int o = 1; o < 256; o <<= 1) {
        int t = (tid >= o) ? sh[tid - o] : 0;
        __syncthreads();
        sh[tid] += t;
        __syncthreads();
    }
    if (i < N) rowptr[i] = sh[tid] - v;
    if (tid == 255) part[blockIdx.x] = sh[255];
}
__global__ void scan2(int* __restrict__ part, int NB)
{
    __shared__ int sh[256];
    int tid = threadIdx.x;
    int v = (tid < NB) ? part[tid] : 0;
    sh[tid] = v; __syncthreads();
    #pragma unroll
    for (int o = 1; o < 256; o <<= 1) {
        int t = (tid >= o) ? sh[tid - o] : 0;
        __syncthreads();
        sh[tid] += t;
        __syncthreads();
    }
    if (tid < NB) part[tid] = sh[tid] - v;
}
__global__ void scan3(int* __restrict__ rowptr, const int* __restrict__ part,
                      int* __restrict__ woff, int N)
{
    int i = blockIdx.x * blockDim.x + threadIdx.x;
    if (i < N) {
        int r = rowptr[i] + part[i >> 8];
        rowptr[i] = r;
        woff[i] = r;
    }
}
__global__ void csr_scatter(const int* __restrict__ src, const int* __restrict__ dst,
                            int* __restrict__ woff, int* __restrict__ csrsrc, int E)
{
    int e = blockIdx.x * blockDim.x + threadIdx.x;
    if (e < E) {
        int p = atomicAdd(&woff[dst[e]], 1);
        csrsrc[p] = src[e];
    }
}

// ================= double-buffered SGEMM 128x128, BK=16, 8x8 micro-tile ========
__global__ void __launch_bounds__(256, 2)
sgemm128(const float* __restrict__ A, const float* __restrict__ W,
         const float* __restrict__ bias, float* __restrict__ C,
         int M, int K, int Nc)
{
    __shared__ float As[2][16][128];
    __shared__ float Bs[2][16][128];

    const int tid = threadIdx.x;
    const int tx = tid & 15;
    const int ty = tid >> 4;
    const int rowBase = blockIdx.y * 128;
    const int colBase = blockIdx.x * 128;

    const int lr = tid & 127;
    const int lc = (tid >> 7) * 4;
    const int wk = tid >> 5;
    const int wc = (tid & 31) * 4;

    const bool aok = (rowBase + lr) < M;
    const float* Arow = A + (size_t)(rowBase + lr) * K;
    const float* Wp = W + colBase + wc;

    const float4 z4 = make_float4(0.f, 0.f, 0.f, 0.f);
    float4 av0 = aok ? *(const float4*)(Arow + lc)     : z4;
    float4 av1 = aok ? *(const float4*)(Arow + lc + 8) : z4;
    float4 bv0 = *(const float4*)(Wp + (size_t)wk * Nc);
    float4 bv1 = *(const float4*)(Wp + (size_t)(wk + 8) * Nc);

    As[0][lc + 0][lr] = av0.x; As[0][lc + 1][lr] = av0.y;
    As[0][lc + 2][lr] = av0.z; As[0][lc + 3][lr] = av0.w;
    As[0][lc + 8][lr] = av1.x; As[0][lc + 9][lr] = av1.y;
    As[0][lc +10][lr] = av1.z; As[0][lc +11][lr] = av1.w;
    *(float4*)&Bs[0][wk][wc]     = bv0;
    *(float4*)&Bs[0][wk + 8][wc] = bv1;
    __syncthreads();

    float acc[8][8];
    #pragma unroll
    for (int i = 0; i < 8; i++)
        #pragma unroll
        for (int j = 0; j < 8; j++) acc[i][j] = 0.f;

    const int T = K >> 4;
    for (int t = 0; t < T; t++) {
        const int buf = t & 1;
        if (t + 1 < T) {
            const int k0 = (t + 1) << 4;
            av0 = aok ? *(const float4*)(Arow + k0 + lc)     : z4;
            av1 = aok ? *(const float4*)(Arow + k0 + lc + 8) : z4;
            bv0 = *(const float4*)(Wp + (size_t)(k0 + wk) * Nc);
            bv1 = *(const float4*)(Wp + (size_t)(k0 + wk + 8) * Nc);
        }
        #pragma unroll
        for (int kk = 0; kk < 16; kk++) {
            float a[8], b[8];
            *(float4*)&a[0] = *(const float4*)&As[buf][kk][ty * 8];
            *(float4*)&a[4] = *(const float4*)&As[buf][kk][ty * 8 + 4];
            *(float4*)&b[0] = *(const float4*)&Bs[buf][kk][tx * 8];
            *(float4*)&b[4] = *(const float4*)&Bs[buf][kk][tx * 8 + 4];
            #pragma unroll
            for (int i = 0; i < 8; i++)
                #pragma unroll
                for (int j = 0; j < 8; j++)
                    acc[i][j] = fmaf(a[i], b[j], acc[i][j]);
        }
        if (t + 1 < T) {
            const int nb = buf ^ 1;
            As[nb][lc + 0][lr] = av0.x; As[nb][lc + 1][lr] = av0.y;
            As[nb][lc + 2][lr] = av0.z; As[nb][lc + 3][lr] = av0.w;
            As[nb][lc + 8][lr] = av1.x; As[nb][lc + 9][lr] = av1.y;
            As[nb][lc +10][lr] = av1.z; As[nb][lc +11][lr] = av1.w;
            *(float4*)&Bs[nb][wk][wc]     = bv0;
            *(float4*)&Bs[nb][wk + 8][wc] = bv1;
            __syncthreads();
        }
    }

    const int cbase = colBase + tx * 8;
    float4 b0 = *(const float4*)(bias + cbase);
    float4 b1 = *(const float4*)(bias + cbase + 4);
    #pragma unroll
    for (int i = 0; i < 8; i++) {
        int r = rowBase + ty * 8 + i;
        if (r >= M) continue;
        float4 o0 = make_float4(acc[i][0] + b0.x, acc[i][1] + b0.y,
                                acc[i][2] + b0.z, acc[i][3] + b0.w);
        float4 o1 = make_float4(acc[i][4] + b1.x, acc[i][5] + b1.y,
                                acc[i][6] + b1.z, acc[i][7] + b1.w);
        *(float4*)(C + (size_t)r * Nc + cbase)     = o0;
        *(float4*)(C + (size_t)r * Nc + cbase + 4) = o1;
    }
}

// ================= small SGEMM for head GEMMs (Nc=32) ==========================
__global__ void sgemm_bias(const float* __restrict__ A, const float* __restrict__ W,
                           const float* __restrict__ bias, float* __restrict__ C,
                           int M, int K, int Nc)
{
    __shared__ float As[16][64];
    __shared__ float Bs[16][64];
    const int tid = threadIdx.x;
    const int tx = tid & 15, ty = tid >> 4;
    const int rowBase = blockIdx.y * 64;
    const int colBase = blockIdx.x * 64;
    const int lr = tid >> 2, lc = (tid & 3) * 4;
    const int wk = tid >> 4, wc = (tid & 15) * 4;

    float acc[4][4];
    #pragma unroll
    for (int i = 0; i < 4; i++)
        #pragma unroll
        for (int j = 0; j < 4; j++) acc[i][j] = 0.f;

    for (int k0 = 0; k0 < K; k0 += 16) {
        float4 av = make_float4(0.f, 0.f, 0.f, 0.f);
        int ar = rowBase + lr;
        if (ar < M) av = *(const float4*)(A + (size_t)ar * K + k0 + lc);
        As[lc + 0][lr] = av.x; As[lc + 1][lr] = av.y;
        As[lc + 2][lr] = av.z; As[lc + 3][lr] = av.w;
        float4 bv = make_float4(0.f, 0.f, 0.f, 0.f);
        int bc = colBase + wc;
        if (bc < Nc) bv = *(const float4*)(W + (size_t)(k0 + wk) * Nc + bc);
        *(float4*)&Bs[wk][wc] = bv;
        __syncthreads();
        #pragma unroll
        for (int kk = 0; kk < 16; kk++) {
            float a[4], b[4];
            *(float4*)a = *(const float4*)&As[kk][ty * 4];
            *(float4*)b = *(const float4*)&Bs[kk][tx * 4];
            #pragma unroll
            for (int i = 0; i < 4; i++)
                #pragma unroll
                for (int j = 0; j < 4; j++)
                    acc[i][j] = fmaf(a[i], b[j], acc[i][j]);
        }
        __syncthreads();
    }
    #pragma unroll
    for (int i = 0; i < 4; i++) {
        int r = rowBase + ty * 4 + i;
        if (r >= M) continue;
        #pragma unroll
        for (int j = 0; j < 4; j++) {
            int c = colBase + tx * 4 + j;
            if (c < Nc) C[(size_t)r * Nc + c] = acc[i][j] + bias[c];
        }
    }
}

// ================= LayerNorm(128) + ELU =========================================
__global__ void ln_elu(float* __restrict__ h, const float* __restrict__ w,
                       const float* __restrict__ b, int N)
{
    int row  = blockIdx.x * (blockDim.x >> 5) + (threadIdx.x >> 5);
    int lane = threadIdx.x & 31;
    if (row >= N) return;
    float4* rp = (float4*)(h + (size_t)row * 128);
    float4 v = rp[lane];
    float s  = v.x + v.y + v.z + v.w;
    float sq = v.x * v.x + v.y * v.y + v.z * v.z + v.w * v.w;
    #pragma unroll
    for (int o = 16; o; o >>= 1) {
        s  += __shfl_xor_sync(0xffffffffu, s,  o);
        sq += __shfl_xor_sync(0xffffffffu, sq, o);
    }
    float mean = s * (1.f / 128.f);
    float var  = sq * (1.f / 128.f) - mean * mean;
    float inv  = rsqrtf(var + 1e-5f);
    float4 wv = ((const float4*)w)[lane];
    float4 bv = ((const float4*)b)[lane];
    float4 o;
    o.x = eluf((v.x - mean) * inv * wv.x + bv.x);
    o.y = eluf((v.y - mean) * inv * wv.y + bv.y);
    o.z = eluf((v.z - mean) * inv * wv.z + bv.z);
    o.w = eluf((v.w - mean) * inv * wv.w + bv.w);
    rp[lane] = o;
}

// ================= SINGLE-PASS fused node-major GATv2 ===========================
// One warp per destination node. For each in-edge: compute alpha (full xl[src]
// already in lane registers), exp, and accumulate BOTH the denominator and the
// unnormalized weighted sum. Normalize once at the end (softmax scale is a
// per-(node,head) constant). Lane l holds head h=l>>3, channels (l&7)*8..+8.
__global__ void gat_node(const float* __restrict__ xl, const float* __restrict__ xr,
                         const int* __restrict__ rowptr, const int* __restrict__ cnt,
                         const int* __restrict__ csrsrc, const float* __restrict__ att,
                         const float* __restrict__ bias,
                         const float* __restrict__ resid, float* __restrict__ out, int N)
{
    int node = (blockIdx.x * blockDim.x + threadIdx.x) >> 5;
    int lane = threadIdx.x & 31;
    if (node >= N) return;
    const int start = rowptr[node];
    const int deg   = cnt[node];

    const float4* at4 = (const float4*)att;
    const float4* xr4 = (const float4*)(xr + (size_t)node * 256);
    const int i4a = lane * 2;
    const float4 w0 = at4[i4a], w1 = at4[i4a + 1];
    const float4 r0 = xr4[i4a], r1 = xr4[i4a + 1];

    float den = 0.f;
    float4 acc0 = make_float4(0.f, 0.f, 0.f, 0.f);
    float4 acc1 = make_float4(0.f, 0.f, 0.f, 0.f);

    for (int i0 = 0; i0 < deg; i0 += 32) {
        int nn = min(32, deg - i0);
        int sReg = (lane < nn) ? csrsrc[start + i0 + lane] : 0;
        for (int i = 0; i < nn; i++) {
            int sv = __shfl_sync(0xffffffffu, sReg, i);
            const float4* xl4 = (const float4*)(xl + (size_t)sv * 256);
            float4 a0 = xl4[i4a], a1 = xl4[i4a + 1];
            float t, al = 0.f;
            t = a0.x + r0.x; t = t >= 0.f ? t : 0.2f * t; al += t * w0.x;
            t = a0.y + r0.y; t = t >= 0.f ? t : 0.2f * t; al += t * w0.y;
            t = a0.z + r0.z; t = t >= 0.f ? t : 0.2f * t; al += t * w0.z;
            t = a0.w + r0.w; t = t >= 0.f ? t : 0.2f * t; al += t * w0.w;
            t = a1.x + r1.x; t = t >= 0.f ? t : 0.2f * t; al += t * w1.x;
            t = a1.y + r1.y; t = t >= 0.f ? t : 0.2f * t; al += t * w1.y;
            t = a1.z + r1.z; t = t >= 0.f ? t : 0.2f * t; al += t * w1.z;
            t = a1.w + r1.w; t = t >= 0.f ? t : 0.2f * t; al += t * w1.w;
            al += __shfl_xor_sync(0xffffffffu, al, 4);
            al += __shfl_xor_sync(0xffffffffu, al, 2);
            al += __shfl_xor_sync(0xffffffffu, al, 1);
            float eav = __expf(al);      // all 8 lanes of this head group hold alpha_h
            den += eav;
            acc0.x = fmaf(eav, a0.x, acc0.x);
            acc0.y = fmaf(eav, a0.y, acc0.y);
            acc0.z = fmaf(eav, a0.z, acc0.z);
            acc0.w = fmaf(eav, a0.w, acc0.w);
            acc1.x = fmaf(eav, a1.x, acc1.x);
            acc1.y = fmaf(eav, a1.y, acc1.y);
            acc1.z = fmaf(eav, a1.z, acc1.z);
            acc1.w = fmaf(eav, a1.w, acc1.w);
        }
    }

    // per-head normalization (den identical across the 8 lanes of a head group)
    const float inv = 0.25f / (den + 1e-16f);
    acc0.x *= inv; acc0.y *= inv; acc0.z *= inv; acc0.w *= inv;
    acc1.x *= inv; acc1.y *= inv; acc1.z *= inv; acc1.w *= inv;

    // cross-head sum: lanes with equal (lane&7) hold same channels, different heads
    #pragma unroll
    for (int mask = 8; mask <= 16; mask <<= 1) {
        acc0.x += __shfl_xor_sync(0xffffffffu, acc0.x, mask);
        acc0.y += __shfl_xor_sync(0xffffffffu, acc0.y, mask);
        acc0.z += __shfl_xor_sync(0xffffffffu, acc0.z, mask);
        acc0.w += __shfl_xor_sync(0xffffffffu, acc0.w, mask);
        acc1.x += __shfl_xor_sync(0xffffffffu, acc1.x, mask);
        acc1.y += __shfl_xor_sync(0xffffffffu, acc1.y, mask);
        acc1.z += __shfl_xor_sync(0xffffffffu, acc1.z, mask);
        acc1.w += __shfl_xor_sync(0xffffffffu, acc1.w, mask);
    }

    if (lane < 8) {
        const int c0 = lane * 8;
        float4 b0 = *(const float4*)(bias + c0);
        float4 b1 = *(const float4*)(bias + c0 + 4);
        float4 rr0 = make_float4(0.f, 0.f, 0.f, 0.f);
        float4 rr1 = make_float4(0.f, 0.f, 0.f, 0.f);
        if (resid) {
            rr0 = *(const float4*)(resid + (size_t)node * 64 + c0);
            rr1 = *(const float4*)(resid + (size_t)node * 64 + c0 + 4);
        }
        float4 o0, o1;
        o0.x = eluf(acc0.x + b0.x + rr0.x);
        o0.y = eluf(acc0.y + b0.y + rr0.y);
        o0.z = eluf(acc0.z + b0.z + rr0.z);
        o0.w = eluf(acc0.w + b0.w + rr0.w);
        o1.x = eluf(acc1.x + b1.x + rr1.x);
        o1.y = eluf(acc1.y + b1.y + rr1.y);
        o1.z = eluf(acc1.z + b1.z + rr1.z);
        o1.w = eluf(acc1.w + b1.w + rr1.w);
        *(float4*)(out + (size_t)node * 64 + c0)     = o0;
        *(float4*)(out + (size_t)node * 64 + c0 + 4) = o1;
    }
}

// ================= launch ========================================================
extern "C" void kernel_launch(void* const* d_in, const int* in_sizes, int n_in,
                              void* d_out, int out_size)
{
    const float* x    = (const float*)d_in[0];
    const int*   ei   = (const int*)  d_in[1];
    const float* W1   = (const float*)d_in[2];
    const float* b1   = (const float*)d_in[3];
    const float* lnw  = (const float*)d_in[4];
    const float* lnb  = (const float*)d_in[5];
    const float* Wl1  = (const float*)d_in[6];
    const float* bl1  = (const float*)d_in[7];
    const float* Wr1  = (const float*)d_in[8];
    const float* br1  = (const float*)d_in[9];
    const float* att1 = (const float*)d_in[10];
    const float* bias1= (const float*)d_in[11];
    const float* Wl2  = (const float*)d_in[12];
    const float* bl2  = (const float*)d_in[13];
    const float* Wr2  = (const float*)d_in[14];
    const float* br2  = (const float*)d_in[15];
    const float* att2 = (const float*)d_in[16];
    const float* bias2= (const float*)d_in[17];
    const float* Wmu  = (const float*)d_in[18];
    const float* bmu  = (const float*)d_in[19];
    const float* Wlv  = (const float*)d_in[20];
    const float* blv  = (const float*)d_in[21];
    float* out = (float*)d_out;

    const int N = in_sizes[0] / 128;
    const int E = in_sizes[1] / 2;
    const int* src = ei;
    const int* dst = ei + E;

    float *h, *xl, *xr, *h1, *h2;
    int *cnt, *rowptr, *woff, *part, *csrsrc;
    cudaGetSymbolAddress((void**)&h,      g_h);
    cudaGetSymbolAddress((void**)&xl,     g_xl);
    cudaGetSymbolAddress((void**)&xr,     g_xr);
    cudaGetSymbolAddress((void**)&h1,     g_h1);
    cudaGetSymbolAddress((void**)&h2,     g_h2);
    cudaGetSymbolAddress((void**)&cnt,    g_cnt);
    cudaGetSymbolAddress((void**)&rowptr, g_rowptr);
    cudaGetSymbolAddress((void**)&woff,   g_woff);
    cudaGetSymbolAddress((void**)&part,   g_part);
    cudaGetSymbolAddress((void**)&csrsrc, g_csrsrc);

    const int rb128 = (N + 127) / 128;
    const int rb64  = (N + 63) / 64;
    const int NB    = (N + 255) / 256;
    const int nodeWarpGrid = (N + 7) / 8;

    // ---- CSR build ----
    csr_zero   <<<NB, 256>>>(cnt, N);
    csr_count  <<<(E + 255) / 256, 256>>>(dst, cnt, E);
    scan1      <<<NB, 256>>>(cnt, rowptr, part, N);
    scan2      <<<1, 256>>>(part, NB);
    scan3      <<<NB, 256>>>(rowptr, part, woff, N);
    csr_scatter<<<(E + 255) / 256, 256>>>(src, dst, woff, csrsrc, E);

    // ---- stage 0 ----
    sgemm128<<<dim3(1, rb128), 256>>>(x, W1, b1, h, N, 128, 128);
    ln_elu<<<(N + 7) / 8, 256>>>(h, lnw, lnb, N);

    // ---- GATv2 layer 1 ----
    sgemm128<<<dim3(2, rb128), 256>>>(h, Wl1, bl1, xl, N, 128, 256);
    sgemm128<<<dim3(2, rb128), 256>>>(h, Wr1, br1, xr, N, 128, 256);
    gat_node<<<nodeWarpGrid, 256>>>(xl, xr, rowptr, cnt, csrsrc, att1,
                                    bias1, nullptr, h1, N);

    // ---- GATv2 layer 2 ----
    sgemm128<<<dim3(2, rb128), 256>>>(h1, Wl2, bl2, xl, N, 64, 256);
    sgemm128<<<dim3(2, rb128), 256>>>(h1, Wr2, br2, xr, N, 64, 256);
    gat_node<<<nodeWarpGrid, 256>>>(xl, xr, rowptr, cnt, csrsrc, att2,
                                    bias2, h1, h2, N);

    // ---- heads ----
    sgemm_bias<<<dim3(1, rb64), 256>>>(h2, Wmu, bmu, out,                  N, 64, 32);
    sgemm_bias<<<dim3(1, rb64), 256>>>(h2, Wlv, blv, out + (size_t)N * 32, N, 64, 32);
}